// round 3
// baseline (speedup 1.0000x reference)
#include <cuda_runtime.h>

// Problem constants
#define SQ 512
#define BB 32
#define HH 1024
#define GG 4096           // 4*HH
#define LL 3
#define MM (SQ*BB)        // 16384 rows for input GEMM
#define NBLK 128          // persistent blocks for recurrence
#define CK 256            // K-chunk for h streaming
#define NCH (HH/CK)       // 4 chunks
#define RP (CK/2 + 2)     // 130 pair-slots per batch row (8B), conflict-free

typedef unsigned long long ull;

// ---- packed f32x2 helpers (sm_100+) ----------------------------------------
__device__ __forceinline__ ull ffma2(ull a, ull b, ull c) {
    ull d;
    asm("fma.rn.f32x2 %0, %1, %2, %3;" : "=l"(d) : "l"(a), "l"(b), "l"(c));
    return d;
}
__device__ __forceinline__ ull dup2(float x) {
    ull d; unsigned u = __float_as_uint(x);
    asm("mov.b64 %0, {%1, %1};" : "=l"(d) : "r"(u));
    return d;
}
__device__ __forceinline__ ull packlo(float x) {   // (x, 0)
    ull d; unsigned u = __float_as_uint(x); unsigned z = 0;
    asm("mov.b64 %0, {%1, %2};" : "=l"(d) : "r"(u), "r"(z));
    return d;
}
__device__ __forceinline__ float sum2(ull v) {
    unsigned lo, hi;
    asm("mov.b64 {%0, %1}, %2;" : "=r"(lo), "=r"(hi) : "l"(v));
    return __uint_as_float(lo) + __uint_as_float(hi);
}

// ------------------------- scratch (device globals) --------------------------
__device__ float g_seqA[(size_t)MM * HH];     // 64 MB (enc emb / ping)
__device__ float g_seqB[(size_t)MM * HH];     // 64 MB (pong)
__device__ float g_seqC[(size_t)MM * HH];     // 64 MB (dec emb / ping)
__device__ float g_G[(size_t)MM * GG];        // 256 MB gates, layout [t][n][b]
__device__ float g_hT[LL * BB * HH];
__device__ float g_cT[LL * BB * HH];
__device__ unsigned g_flags[NBLK];            // grid-barrier flags

// ------------------------- grid barrier (flag array, no atomics) -------------
// Each block release-stores its arrival count; warp 0 acquire-polls all flags.
// Targets are monotone within a replay (per-launch base), reset kernel zeroes
// flags at end of each replay so graph replays stay correct.
__device__ __forceinline__ void grid_barrier(unsigned target) {
    __syncthreads();
    const int tid = threadIdx.x;
    if (tid < 32) {
        if (tid == 0) {
            asm volatile("st.release.gpu.global.u32 [%0], %1;"
                         :: "l"(&g_flags[blockIdx.x]), "r"(target) : "memory");
        }
        const unsigned* f = g_flags;
        for (;;) {
            unsigned v0, v1, v2, v3;
            asm volatile("ld.acquire.gpu.global.u32 %0, [%1];" : "=r"(v0) : "l"(f + tid));
            asm volatile("ld.acquire.gpu.global.u32 %0, [%1];" : "=r"(v1) : "l"(f + tid + 32));
            asm volatile("ld.acquire.gpu.global.u32 %0, [%1];" : "=r"(v2) : "l"(f + tid + 64));
            asm volatile("ld.acquire.gpu.global.u32 %0, [%1];" : "=r"(v3) : "l"(f + tid + 96));
            bool ok = (v0 >= target) & (v1 >= target) & (v2 >= target) & (v3 >= target);
            if (__all_sync(0xffffffffu, ok)) break;
        }
    }
    __syncthreads();
}

__global__ void reset_flags_kernel() {
    if (threadIdx.x < NBLK) g_flags[threadIdx.x] = 0u;
}

// ------------------------- embedding gather ----------------------------------
__global__ void gather_kernel(const int* __restrict__ x,
                              const float* __restrict__ emb,
                              float* __restrict__ out) {
    const int total = MM * (HH / 4);
    for (int i = blockIdx.x * blockDim.x + threadIdx.x; i < total;
         i += gridDim.x * blockDim.x) {
        int row = i >> 8;
        int col = i & 255;
        int tok = __ldg(x + row);
        float4 v = __ldg(((const float4*)(emb + (size_t)tok * HH)) + col);
        ((float4*)out)[i] = v;
    }
}

// ------------------------- input GEMM ----------------------------------------
// C2[t][n][b] = (A[m=(t,b)] @ W[n]^T + bias[n]), transposed epilogue so the
// recurrence reads gate preactivations coalesced (lane = batch).
__global__ __launch_bounds__(256) void igemm_kernel(
    const float* __restrict__ A, const float* __restrict__ W,
    const float* __restrict__ bias, float* __restrict__ C2) {
    __shared__ float As[16][132];
    __shared__ float Bs[16][132];
    const int tid = threadIdx.x;
    const int bm = blockIdx.y * 128;
    const int bn = blockIdx.x * 128;
    const int tx = tid & 15;
    const int ty = tid >> 4;
    const int r0 = tid >> 2;
    const int kq0 = (tid & 3) << 2;

    ull acc[8][4];
#pragma unroll
    for (int i = 0; i < 8; ++i)
#pragma unroll
        for (int j = 0; j < 4; ++j) acc[i][j] = 0ull;

    for (int k0 = 0; k0 < HH; k0 += 16) {
#pragma unroll
        for (int j = 0; j < 2; ++j) {
            int row = r0 + j * 64;
            float4 va = __ldg((const float4*)(A + (size_t)(bm + row) * HH + k0 + kq0));
            As[kq0 + 0][row] = va.x; As[kq0 + 1][row] = va.y;
            As[kq0 + 2][row] = va.z; As[kq0 + 3][row] = va.w;
            float4 vb = __ldg((const float4*)(W + (size_t)(bn + row) * HH + k0 + kq0));
            Bs[kq0 + 0][row] = vb.x; Bs[kq0 + 1][row] = vb.y;
            Bs[kq0 + 2][row] = vb.z; Bs[kq0 + 3][row] = vb.w;
        }
        __syncthreads();
#pragma unroll
        for (int k = 0; k < 16; ++k) {
            float ra[8];
            *(float4*)(ra)     = *(const float4*)(&As[k][ty * 8]);
            *(float4*)(ra + 4) = *(const float4*)(&As[k][ty * 8 + 4]);
            ulonglong2 rb0 = *(const ulonglong2*)(&Bs[k][tx * 8]);
            ulonglong2 rb1 = *(const ulonglong2*)(&Bs[k][tx * 8 + 4]);
#pragma unroll
            for (int i = 0; i < 8; ++i) {
                ull rad = dup2(ra[i]);
                acc[i][0] = ffma2(rad, rb0.x, acc[i][0]);
                acc[i][1] = ffma2(rad, rb0.y, acc[i][1]);
                acc[i][2] = ffma2(rad, rb1.x, acc[i][2]);
                acc[i][3] = ffma2(rad, rb1.y, acc[i][3]);
            }
        }
        __syncthreads();
    }
    // bias for this thread's 8 n's
    float bv[8];
    *(float4*)(bv)     = __ldg((const float4*)(bias + bn + tx * 8));
    *(float4*)(bv + 4) = __ldg((const float4*)(bias + bn + tx * 8 + 4));
#pragma unroll
    for (int i = 0; i < 8; ++i) {
        int m = bm + ty * 8 + i;
        int t = m >> 5;
        int b = m & 31;
        float* crow = C2 + (size_t)t * GG * BB + b;
#pragma unroll
        for (int jp = 0; jp < 4; ++jp) {
            int n = bn + tx * 8 + jp * 2;
            unsigned lo, hi;
            asm("mov.b64 {%0, %1}, %2;" : "=r"(lo), "=r"(hi) : "l"(acc[i][jp]));
            __stcg(crow + (size_t)n * BB,       __uint_as_float(lo) + bv[jp * 2]);
            __stcg(crow + (size_t)(n + 1) * BB, __uint_as_float(hi) + bv[jp * 2 + 1]);
        }
    }
}

// ------------------------- persistent recurrence -----------------------------
__global__ __launch_bounds__(256, 1) void recur_kernel(
    const float* __restrict__ Gin,   // [SQ][GG][BB]
    const float* __restrict__ Whh,   // [GG, HH]
    const float* __restrict__ h0,    // [BB,HH] or null (zeros)
    const float* __restrict__ c0,    // [BB,HH] or null (zeros)
    float* __restrict__ out,         // [SQ,BB,HH]
    float* __restrict__ hT,
    float* __restrict__ cT,
    unsigned flag_base) {
    extern __shared__ __align__(16) char shraw[];
    float* Wsh = (float*)shraw;                           // [32][HH] 128 KB
    ull*   hsh = (ull*)(shraw + 32 * HH * sizeof(float)); // [2][32][RP] 66.56 KB
    const int tid = threadIdx.x;
    const int u0 = blockIdx.x * 8;
    const int w = tid >> 5;
    const int lane = tid & 31;

    // Load this block's 32 Whh rows (gate-major local rows: lr = gate*8 + uu)
    for (int i = tid; i < 32 * 256; i += 256) {
        int lr = i >> 8;
        int kq = i & 255;
        int gam = lr >> 3, uu = lr & 7;
        float4 v = __ldg((const float4*)(Whh + (size_t)(gam * HH + u0 + uu) * HH) + kq);
        ((float4*)(Wsh + (size_t)lr * HH))[kq] = v;
    }
    float c = (c0 != nullptr) ? c0[lane * HH + u0 + w] : 0.f;
    __syncthreads();

    const float* w0p = Wsh + (size_t)(0 * 8 + w) * HH;
    const float* w1p = Wsh + (size_t)(1 * 8 + w) * HH;
    const float* w2p = Wsh + (size_t)(2 * 8 + w) * HH;
    const float* w3p = Wsh + (size_t)(3 * 8 + w) * HH;

    const int ldb = tid >> 6;        // base batch row for h loads (0..3)
    const int ldf = tid & 63;        // float4 column within chunk

    float hlast = 0.f;
    for (int t = 0; t < SQ; ++t) {
        const float* hp = (t == 0) ? h0 : (out + (size_t)(t - 1) * BB * HH);
        // gate preactivations (coalesced: lane = batch)
        ull acc0, acc1, acc2, acc3;
        {
            const float* gb = Gin + ((size_t)t * GG + (u0 + w)) * BB + lane;
            acc0 = packlo(__ldcg(gb));
            acc1 = packlo(__ldcg(gb + (size_t)HH * BB));
            acc2 = packlo(__ldcg(gb + (size_t)2 * HH * BB));
            acc3 = packlo(__ldcg(gb + (size_t)3 * HH * BB));
        }
        if (hp != nullptr) {
            float4 r[8];
#pragma unroll
            for (int j = 0; j < 8; ++j) {
                int b = ldb + j * 4;
                r[j] = __ldcg((const float4*)(hp + (size_t)b * HH) + ldf);
            }
            for (int cI = 0; cI < NCH; ++cI) {
                const int p = cI & 1;
                ull* hbuf = hsh + (size_t)p * 32 * RP;
#pragma unroll
                for (int j = 0; j < 8; ++j) {
                    int b = ldb + j * 4;
                    *(float4*)(hbuf + (size_t)b * RP + 2 * ldf) = r[j];
                }
                __syncthreads();
                if (cI + 1 < NCH) {
                    const float* hpc = hp + (cI + 1) * CK;
#pragma unroll
                    for (int j = 0; j < 8; ++j) {
                        int b = ldb + j * 4;
                        r[j] = __ldcg((const float4*)(hpc + (size_t)b * HH) + ldf);
                    }
                }
                const int k0 = cI * CK;
                const ull* hb = hbuf + (size_t)lane * RP;
                const ulonglong2* w0d = (const ulonglong2*)(w0p + k0);
                const ulonglong2* w1d = (const ulonglong2*)(w1p + k0);
                const ulonglong2* w2d = (const ulonglong2*)(w2p + k0);
                const ulonglong2* w3d = (const ulonglong2*)(w3p + k0);
#pragma unroll 8
                for (int q = 0; q < CK / 4; ++q) {
                    ulonglong2 W0 = w0d[q];
                    ulonglong2 W1 = w1d[q];
                    ulonglong2 W2 = w2d[q];
                    ulonglong2 W3 = w3d[q];
                    ulonglong2 Hp = *(const ulonglong2*)(hb + 2 * q);
                    acc0 = ffma2(W0.x, Hp.x, acc0);
                    acc1 = ffma2(W1.x, Hp.x, acc1);
                    acc2 = ffma2(W2.x, Hp.x, acc2);
                    acc3 = ffma2(W3.x, Hp.x, acc3);
                    acc0 = ffma2(W0.y, Hp.y, acc0);
                    acc1 = ffma2(W1.y, Hp.y, acc1);
                    acc2 = ffma2(W2.y, Hp.y, acc2);
                    acc3 = ffma2(W3.y, Hp.y, acc3);
                }
                __syncthreads();
            }
        }
        float a0 = sum2(acc0);
        float a1 = sum2(acc1);
        float a2 = sum2(acc2);
        float a3 = sum2(acc3);
        float iv = 1.f / (1.f + expf(-a0));
        float fv = 1.f / (1.f + expf(-a1));
        float gv = tanhf(a2);
        float ov = 1.f / (1.f + expf(-a3));
        c = fv * c + iv * gv;
        float hv = ov * tanhf(c);
        __stcg(out + (size_t)t * BB * HH + (size_t)lane * HH + u0 + w, hv);
        hlast = hv;
        if (t != SQ - 1) grid_barrier(flag_base + (unsigned)t + 1u);
    }
    if (hT != nullptr) hT[lane * HH + u0 + w] = hlast;
    if (cT != nullptr) cT[lane * HH + u0 + w] = c;
}

// ------------------------- launch --------------------------------------------
extern "C" void kernel_launch(void* const* d_in, const int* in_sizes, int n_in,
                              void* d_out, int out_size) {
    const int*   x       = (const int*)d_in[0];
    const float* emb_enc = (const float*)d_in[1];
    const float* enc_Wih = (const float*)d_in[2];
    const float* enc_Whh = (const float*)d_in[3];
    const float* enc_b   = (const float*)d_in[4];
    const float* emb_dec = (const float*)d_in[5];
    const float* dec_Wih = (const float*)d_in[6];
    const float* dec_Whh = (const float*)d_in[7];
    const float* dec_b   = (const float*)d_in[8];
    float* out = (float*)d_out;

    float *seqA, *seqB, *seqC, *G, *hT, *cT;
    cudaGetSymbolAddress((void**)&seqA, g_seqA);
    cudaGetSymbolAddress((void**)&seqB, g_seqB);
    cudaGetSymbolAddress((void**)&seqC, g_seqC);
    cudaGetSymbolAddress((void**)&G,    g_G);
    cudaGetSymbolAddress((void**)&hT,   g_hT);
    cudaGetSymbolAddress((void**)&cT,   g_cT);

    const int recur_smem = 32 * HH * (int)sizeof(float)
                         + 2 * 32 * RP * (int)sizeof(ull);   // 197632 B
    cudaFuncSetAttribute(recur_kernel,
                         cudaFuncAttributeMaxDynamicSharedMemorySize, recur_smem);

    dim3 ig_grid(GG / 128, MM / 128);  // (32, 128)

    // Both gathers first (also puts recur_kernel at ncu's -s 5 capture slot).
    gather_kernel<<<2048, 256>>>(x, emb_enc, seqA);
    gather_kernel<<<2048, 256>>>(x, emb_dec, seqC);

    unsigned launch_idx = 0;

    // ---------------- encoder: A -> B -> A -> B ----------------
    float* cur = seqA;
    float* nxt = seqB;
    for (int l = 0; l < LL; ++l) {
        igemm_kernel<<<ig_grid, 256>>>(cur, enc_Wih + (size_t)l * GG * HH,
                                       enc_b + (size_t)l * GG, G);
        recur_kernel<<<NBLK, 256, recur_smem>>>(
            G, enc_Whh + (size_t)l * GG * HH, nullptr, nullptr,
            nxt, hT + (size_t)l * BB * HH, cT + (size_t)l * BB * HH,
            launch_idx * 1024u);
        ++launch_idx;
        float* tmp = cur; cur = nxt; nxt = tmp;
    }

    // ---------------- decoder: C -> A -> C -> out ----------------
    cur = seqC; nxt = seqA;
    for (int l = 0; l < LL; ++l) {
        igemm_kernel<<<ig_grid, 256>>>(cur, dec_Wih + (size_t)l * GG * HH,
                                       dec_b + (size_t)l * GG, G);
        float* target = (l == LL - 1) ? out : nxt;
        recur_kernel<<<NBLK, 256, recur_smem>>>(
            G, dec_Whh + (size_t)l * GG * HH,
            hT + (size_t)l * BB * HH, cT + (size_t)l * BB * HH,
            target, nullptr, nullptr,
            launch_idx * 1024u);
        ++launch_idx;
        nxt = cur; cur = target;
    }

    // Reset barrier flags so the next graph replay starts clean.
    reset_flags_kernel<<<1, 128>>>();
}

// round 4
// speedup vs baseline: 1.2498x; 1.2498x over previous
#include <cuda_runtime.h>

// Problem constants
#define SQ 512
#define BB 32
#define HH 1024
#define GG 4096           // 4*HH
#define LL 3
#define MM (SQ*BB)        // 16384 rows for input GEMM
#define NBLK 128          // persistent blocks for recurrence
#define HPAD 33           // float4 pitch for h chunk rows

typedef unsigned long long ull;

// ---- packed f32x2 helpers (sm_100+) ----------------------------------------
__device__ __forceinline__ ull ffma2(ull a, ull b, ull c) {
    ull d;
    asm("fma.rn.f32x2 %0, %1, %2, %3;" : "=l"(d) : "l"(a), "l"(b), "l"(c));
    return d;
}
__device__ __forceinline__ ull add2(ull a, ull b) {
    ull d;
    asm("add.rn.f32x2 %0, %1, %2;" : "=l"(d) : "l"(a), "l"(b));
    return d;
}
__device__ __forceinline__ ull dup2(float x) {
    ull d; unsigned u = __float_as_uint(x);
    asm("mov.b64 %0, {%1, %1};" : "=l"(d) : "r"(u));
    return d;
}
__device__ __forceinline__ float sum2(ull v) {
    unsigned lo, hi;
    asm("mov.b64 {%0, %1}, %2;" : "=r"(lo), "=r"(hi) : "l"(v));
    return __uint_as_float(lo) + __uint_as_float(hi);
}

// ------------------------- scratch (device globals) --------------------------
__device__ float g_seqA[(size_t)MM * HH];     // 64 MB
__device__ float g_seqB[(size_t)MM * HH];     // 64 MB
__device__ float g_seqC[(size_t)MM * HH];     // 64 MB
__device__ float g_G[(size_t)MM * GG];        // 256 MB gates, layout [t][n][b]
__device__ float g_hT[LL * BB * HH];
__device__ float g_cT[LL * BB * HH];
__device__ unsigned g_flags[NBLK];
__device__ unsigned g_go;

// ------------------------- grid barrier (two-level flag/go) ------------------
__device__ __forceinline__ void grid_barrier(unsigned target) {
    __syncthreads();
    if (threadIdx.x == 0) {
        asm volatile("st.release.gpu.global.u32 [%0], %1;"
                     :: "l"(&g_flags[blockIdx.x]), "r"(target) : "memory");
    }
    if (blockIdx.x == 0) {
        if (threadIdx.x < 32) {
            const unsigned* f = g_flags;
            for (;;) {
                unsigned v0, v1, v2, v3;
                asm volatile("ld.acquire.gpu.global.u32 %0, [%1];" : "=r"(v0) : "l"(f + threadIdx.x));
                asm volatile("ld.acquire.gpu.global.u32 %0, [%1];" : "=r"(v1) : "l"(f + threadIdx.x + 32));
                asm volatile("ld.acquire.gpu.global.u32 %0, [%1];" : "=r"(v2) : "l"(f + threadIdx.x + 64));
                asm volatile("ld.acquire.gpu.global.u32 %0, [%1];" : "=r"(v3) : "l"(f + threadIdx.x + 96));
                bool ok = (v0 >= target) & (v1 >= target) & (v2 >= target) & (v3 >= target);
                if (__all_sync(0xffffffffu, ok)) break;
            }
            if (threadIdx.x == 0) {
                asm volatile("st.release.gpu.global.u32 [%0], %1;"
                             :: "l"(&g_go), "r"(target) : "memory");
            }
        }
    } else {
        if (threadIdx.x == 0) {
            unsigned v;
            do {
                asm volatile("ld.acquire.gpu.global.u32 %0, [%1];" : "=r"(v) : "l"(&g_go));
            } while (v < target);
        }
    }
    __syncthreads();
}

__global__ void reset_flags_kernel() {
    if (threadIdx.x < NBLK) g_flags[threadIdx.x] = 0u;
    if (threadIdx.x == 0) g_go = 0u;
}

// ------------------------- embedding gather ----------------------------------
__global__ void gather_kernel(const int* __restrict__ x,
                              const float* __restrict__ emb,
                              float* __restrict__ out) {
    const int total = MM * (HH / 4);
    for (int i = blockIdx.x * blockDim.x + threadIdx.x; i < total;
         i += gridDim.x * blockDim.x) {
        int row = i >> 8;
        int col = i & 255;
        int tok = __ldg(x + row);
        float4 v = __ldg(((const float4*)(emb + (size_t)tok * HH)) + col);
        ((float4*)out)[i] = v;
    }
}

// ------------------------- input GEMM ----------------------------------------
// C2[t][n][b] = A[m=(t,b)] @ W[n]^T + bias[n]; epilogue staged through SMEM
// so global stores are fully coalesced despite the [n][b] transpose.
__global__ __launch_bounds__(256) void igemm_kernel(
    const float* __restrict__ A, const float* __restrict__ W,
    const float* __restrict__ bias, float* __restrict__ C2) {
    __shared__ float As[16][132];
    __shared__ float Bs[16][132];
    __shared__ float stage[128 * 33];       // [n_local][b] pitch 33
    const int tid = threadIdx.x;
    const int bm = blockIdx.y * 128;
    const int bn = blockIdx.x * 128;
    const int tx = tid & 15;
    const int ty = tid >> 4;
    const int r0 = tid >> 2;
    const int kq0 = (tid & 3) << 2;

    ull acc[8][4];
#pragma unroll
    for (int i = 0; i < 8; ++i)
#pragma unroll
        for (int j = 0; j < 4; ++j) acc[i][j] = 0ull;

    for (int k0 = 0; k0 < HH; k0 += 16) {
#pragma unroll
        for (int j = 0; j < 2; ++j) {
            int row = r0 + j * 64;
            float4 va = __ldg((const float4*)(A + (size_t)(bm + row) * HH + k0 + kq0));
            As[kq0 + 0][row] = va.x; As[kq0 + 1][row] = va.y;
            As[kq0 + 2][row] = va.z; As[kq0 + 3][row] = va.w;
            float4 vb = __ldg((const float4*)(W + (size_t)(bn + row) * HH + k0 + kq0));
            Bs[kq0 + 0][row] = vb.x; Bs[kq0 + 1][row] = vb.y;
            Bs[kq0 + 2][row] = vb.z; Bs[kq0 + 3][row] = vb.w;
        }
        __syncthreads();
#pragma unroll
        for (int k = 0; k < 16; ++k) {
            float ra[8];
            *(float4*)(ra)     = *(const float4*)(&As[k][ty * 8]);
            *(float4*)(ra + 4) = *(const float4*)(&As[k][ty * 8 + 4]);
            ulonglong2 rb0 = *(const ulonglong2*)(&Bs[k][tx * 8]);
            ulonglong2 rb1 = *(const ulonglong2*)(&Bs[k][tx * 8 + 4]);
#pragma unroll
            for (int i = 0; i < 8; ++i) {
                ull rad = dup2(ra[i]);
                acc[i][0] = ffma2(rad, rb0.x, acc[i][0]);
                acc[i][1] = ffma2(rad, rb0.y, acc[i][1]);
                acc[i][2] = ffma2(rad, rb1.x, acc[i][2]);
                acc[i][3] = ffma2(rad, rb1.y, acc[i][3]);
            }
        }
        __syncthreads();
    }
    // staged transposed epilogue
    float bv[8];
    *(float4*)(bv)     = __ldg((const float4*)(bias + bn + tx * 8));
    *(float4*)(bv + 4) = __ldg((const float4*)(bias + bn + tx * 8 + 4));
    const int t0 = bm >> 5;
    const int tyq = ty >> 2;          // which t this thread's rows belong to
    const int brow = (ty & 3) * 8;    // base batch within that t
    for (int tg = 0; tg < 4; ++tg) {
        if (tyq == tg) {
#pragma unroll
            for (int i = 0; i < 8; ++i) {
                int b = brow + i;
#pragma unroll
                for (int jp = 0; jp < 4; ++jp) {
                    unsigned lo, hi;
                    asm("mov.b64 {%0, %1}, %2;" : "=r"(lo), "=r"(hi) : "l"(acc[i][jp]));
                    int nl = tx * 8 + jp * 2;
                    stage[nl * 33 + b]       = __uint_as_float(lo) + bv[jp * 2];
                    stage[(nl + 1) * 33 + b] = __uint_as_float(hi) + bv[jp * 2 + 1];
                }
            }
        }
        __syncthreads();
        float* gbase = C2 + ((size_t)(t0 + tg) * GG + bn) * BB;
        for (int gidx = tid; gidx < 4096; gidx += 256) {
            int nl = gidx >> 5;
            int b = gidx & 31;
            __stcg(gbase + gidx, stage[nl * 33 + b]);
        }
        __syncthreads();
    }
}

// ------------------------- persistent recurrence -----------------------------
// 128 blocks x 256 threads; block owns 8 units (32 gate rows in SMEM).
// Compute role: thread (pg=K-group, ug4=row-quad, b4) -> 4x4 accumulator tile
// over a 256-K slice. h staged per 256-K chunk as [kq][b] float4 (dense LDS).
// Final role: thread (fu, fb) reduces 4 partials x 4 gates, does cell update.
__global__ __launch_bounds__(256, 1) void recur_kernel(
    const float* __restrict__ Gin,   // [SQ][GG][BB]
    const float* __restrict__ Whh,   // [GG, HH]
    const float* __restrict__ h0,
    const float* __restrict__ c0,
    float* __restrict__ out,         // [SQ,BB,HH]
    float* __restrict__ hT,
    float* __restrict__ cT,
    unsigned flag_base) {
    extern __shared__ __align__(16) char shraw[];
    float*  Wsh = (float*)shraw;                              // [32][1024] 128 KB
    float4* hb  = (float4*)(shraw + 32 * HH * sizeof(float)); // [2][64][33] f4
    ull*    part = (ull*)hb;                                  // alias buffer 0

    const int tid = threadIdx.x;
    const int u0 = blockIdx.x * 8;
    // compute role
    const int b4  = tid & 7;
    const int ug4 = (tid >> 3) & 7;
    const int pg  = tid >> 6;
    // final role
    const int fu = tid >> 5;
    const int fb = tid & 31;
    // loader role
    const int lb = tid >> 3;
    const int lj = tid & 7;

    // Load W rows (lr = gate*8 + unit)
    for (int i = tid; i < 32 * 256; i += 256) {
        int lr = i >> 8;
        int kq = i & 255;
        int gam = lr >> 3, uu = lr & 7;
        float4 v = __ldg((const float4*)(Whh + (size_t)(gam * HH + u0 + uu) * HH) + kq);
        ((float4*)(Wsh + (size_t)lr * HH))[kq] = v;
    }
    float c = (c0 != nullptr) ? c0[fb * HH + u0 + fu] : 0.f;
    __syncthreads();

    const float* wbase = Wsh + (size_t)(ug4 * 4) * HH;

    float hlast = 0.f;
    for (int t = 0; t < SQ; ++t) {
        const float* hp = (t == 0) ? h0 : (out + (size_t)(t - 1) * BB * HH);
        // gate preactivations (coalesced: lane = batch)
        float a0, a1, a2, a3;
        {
            const float* gb = Gin + ((size_t)t * GG + (u0 + fu)) * BB + fb;
            a0 = __ldcg(gb);
            a1 = __ldcg(gb + (size_t)HH * BB);
            a2 = __ldcg(gb + (size_t)2 * HH * BB);
            a3 = __ldcg(gb + (size_t)3 * HH * BB);
        }
        ull acc[4][4];
#pragma unroll
        for (int rr = 0; rr < 4; ++rr)
#pragma unroll
            for (int ss = 0; ss < 4; ++ss) acc[rr][ss] = 0ull;

        if (hp != nullptr) {
            float4 r[8];
#pragma unroll
            for (int m = 0; m < 8; ++m)
                r[m] = __ldcg((const float4*)(hp + (size_t)lb * HH) + lj + 8 * m);
            for (int cI = 0; cI < 4; ++cI) {
                float4* buf = hb + (size_t)(cI & 1) * (64 * HPAD);
#pragma unroll
                for (int m = 0; m < 8; ++m)
                    buf[(lj + 8 * m) * HPAD + lb] = r[m];
                __syncthreads();
                if (cI < 3) {
                    const float* hpc = hp + (cI + 1) * 256;
#pragma unroll
                    for (int m = 0; m < 8; ++m)
                        r[m] = __ldcg((const float4*)(hpc + (size_t)lb * HH) + lj + 8 * m);
                }
                const float* wk = wbase + cI * 256 + pg * 64;
                const float4* hk = buf + (pg * 16) * HPAD + b4;
#pragma unroll 8
                for (int i = 0; i < 16; ++i) {
                    ulonglong2 Wv[4];
#pragma unroll
                    for (int rr = 0; rr < 4; ++rr)
                        Wv[rr] = *(const ulonglong2*)(wk + (size_t)rr * HH + i * 4);
#pragma unroll
                    for (int ss = 0; ss < 4; ++ss) {
                        float4 hv4 = hk[i * HPAD + 8 * ss];
                        ulonglong2 Hv = *(ulonglong2*)&hv4;
                        acc[0][ss] = ffma2(Wv[0].x, Hv.x, acc[0][ss]);
                        acc[1][ss] = ffma2(Wv[1].x, Hv.x, acc[1][ss]);
                        acc[2][ss] = ffma2(Wv[2].x, Hv.x, acc[2][ss]);
                        acc[3][ss] = ffma2(Wv[3].x, Hv.x, acc[3][ss]);
                        acc[0][ss] = ffma2(Wv[0].y, Hv.y, acc[0][ss]);
                        acc[1][ss] = ffma2(Wv[1].y, Hv.y, acc[1][ss]);
                        acc[2][ss] = ffma2(Wv[2].y, Hv.y, acc[2][ss]);
                        acc[3][ss] = ffma2(Wv[3].y, Hv.y, acc[3][ss]);
                    }
                }
            }
        }
        // write partials (buffer 0 region; last compute chunk used buffer 1)
#pragma unroll
        for (int rr = 0; rr < 4; ++rr)
#pragma unroll
            for (int ss = 0; ss < 4; ++ss)
                part[(pg * 32 + ug4 * 4 + rr) * 32 + b4 + 8 * ss] = acc[rr][ss];
        __syncthreads();
        // final reduction: 4 partials x 4 gates
        ull s0 = 0, s1 = 0, s2 = 0, s3 = 0;
#pragma unroll
        for (int p = 0; p < 4; ++p) {
            const ull* pp = part + p * 1024 + fb;
            s0 = add2(s0, pp[(0 * 8 + fu) * 32]);
            s1 = add2(s1, pp[(1 * 8 + fu) * 32]);
            s2 = add2(s2, pp[(2 * 8 + fu) * 32]);
            s3 = add2(s3, pp[(3 * 8 + fu) * 32]);
        }
        a0 += sum2(s0);
        a1 += sum2(s1);
        a2 += sum2(s2);
        a3 += sum2(s3);
        float iv = 1.f / (1.f + expf(-a0));
        float fv = 1.f / (1.f + expf(-a1));
        float gv = tanhf(a2);
        float ov = 1.f / (1.f + expf(-a3));
        c = fv * c + iv * gv;
        float hv = ov * tanhf(c);
        __stcg(out + (size_t)t * BB * HH + (size_t)fb * HH + u0 + fu, hv);
        hlast = hv;
        if (t != SQ - 1) grid_barrier(flag_base + (unsigned)t + 1u);
        else __syncthreads();   // protect partial buffer before next step's reuse (none; end)
    }
    if (hT != nullptr) hT[fb * HH + u0 + fu] = hlast;
    if (cT != nullptr) cT[fb * HH + u0 + fu] = c;
}

// ------------------------- launch --------------------------------------------
extern "C" void kernel_launch(void* const* d_in, const int* in_sizes, int n_in,
                              void* d_out, int out_size) {
    const int*   x       = (const int*)d_in[0];
    const float* emb_enc = (const float*)d_in[1];
    const float* enc_Wih = (const float*)d_in[2];
    const float* enc_Whh = (const float*)d_in[3];
    const float* enc_b   = (const float*)d_in[4];
    const float* emb_dec = (const float*)d_in[5];
    const float* dec_Wih = (const float*)d_in[6];
    const float* dec_Whh = (const float*)d_in[7];
    const float* dec_b   = (const float*)d_in[8];
    float* out = (float*)d_out;

    float *seqA, *seqB, *seqC, *G, *hT, *cT;
    cudaGetSymbolAddress((void**)&seqA, g_seqA);
    cudaGetSymbolAddress((void**)&seqB, g_seqB);
    cudaGetSymbolAddress((void**)&seqC, g_seqC);
    cudaGetSymbolAddress((void**)&G,    g_G);
    cudaGetSymbolAddress((void**)&hT,   g_hT);
    cudaGetSymbolAddress((void**)&cT,   g_cT);

    const int recur_smem = 32 * HH * (int)sizeof(float)
                         + 2 * 64 * HPAD * (int)sizeof(float4);   // 198656 B
    cudaFuncSetAttribute(recur_kernel,
                         cudaFuncAttributeMaxDynamicSharedMemorySize, recur_smem);

    dim3 ig_grid(GG / 128, MM / 128);  // (32, 128)

    gather_kernel<<<2048, 256>>>(x, emb_enc, seqA);
    gather_kernel<<<2048, 256>>>(x, emb_dec, seqC);

    unsigned launch_idx = 0;

    // ---------------- encoder ----------------
    float* cur = seqA;
    float* nxt = seqB;
    for (int l = 0; l < LL; ++l) {
        igemm_kernel<<<ig_grid, 256>>>(cur, enc_Wih + (size_t)l * GG * HH,
                                       enc_b + (size_t)l * GG, G);
        recur_kernel<<<NBLK, 256, recur_smem>>>(
            G, enc_Whh + (size_t)l * GG * HH, nullptr, nullptr,
            nxt, hT + (size_t)l * BB * HH, cT + (size_t)l * BB * HH,
            launch_idx * 1024u);
        ++launch_idx;
        float* tmp = cur; cur = nxt; nxt = tmp;
    }

    // ---------------- decoder ----------------
    cur = seqC; nxt = seqA;
    for (int l = 0; l < LL; ++l) {
        igemm_kernel<<<ig_grid, 256>>>(cur, dec_Wih + (size_t)l * GG * HH,
                                       dec_b + (size_t)l * GG, G);
        float* target = (l == LL - 1) ? out : nxt;
        recur_kernel<<<NBLK, 256, recur_smem>>>(
            G, dec_Whh + (size_t)l * GG * HH,
            hT + (size_t)l * BB * HH, cT + (size_t)l * BB * HH,
            target, nullptr, nullptr,
            launch_idx * 1024u);
        ++launch_idx;
        nxt = cur; cur = target;
    }

    reset_flags_kernel<<<1, 128>>>();
}

// round 5
// speedup vs baseline: 1.3175x; 1.0542x over previous
#include <cuda_runtime.h>

// Problem constants
#define SQ 512
#define BB 32
#define HH 1024
#define GG 4096           // 4*HH
#define LL 3
#define MM (SQ*BB)        // 16384 rows for input GEMM
#define NBLK 128          // persistent blocks for recurrence
#define HPITCH 1028       // Wsh row pitch in floats (odd multiple of 16B)

typedef unsigned long long ull;

// ---- packed f32x2 helpers (sm_100+) ----------------------------------------
__device__ __forceinline__ ull ffma2(ull a, ull b, ull c) {
    ull d;
    asm("fma.rn.f32x2 %0, %1, %2, %3;" : "=l"(d) : "l"(a), "l"(b), "l"(c));
    return d;
}
__device__ __forceinline__ ull dup2(float x) {
    ull d; unsigned u = __float_as_uint(x);
    asm("mov.b64 %0, {%1, %1};" : "=l"(d) : "r"(u));
    return d;
}
__device__ __forceinline__ float sum2(ull v) {
    unsigned lo, hi;
    asm("mov.b64 {%0, %1}, %2;" : "=r"(lo), "=r"(hi) : "l"(v));
    return __uint_as_float(lo) + __uint_as_float(hi);
}

// ------------------------- scratch (device globals) --------------------------
__device__ float g_seqA[(size_t)MM * HH];     // 64 MB
__device__ float g_seqB[(size_t)MM * HH];     // 64 MB
__device__ float g_seqC[(size_t)MM * HH];     // 64 MB
__device__ float g_G[(size_t)MM * GG];        // 256 MB gates, natural [m][n]
__device__ float g_hT[LL * BB * HH];
__device__ float g_cT[LL * BB * HH];
__device__ unsigned g_flags[NBLK];

// ------------------------- grid barrier (flag array, all-poll) ---------------
__device__ __forceinline__ void grid_barrier(unsigned target) {
    __syncthreads();
    const int tid = threadIdx.x;
    if (tid < 32) {
        if (tid == 0) {
            asm volatile("st.release.gpu.global.u32 [%0], %1;"
                         :: "l"(&g_flags[blockIdx.x]), "r"(target) : "memory");
        }
        const unsigned* f = g_flags;
        for (;;) {
            unsigned v0, v1, v2, v3;
            asm volatile("ld.acquire.gpu.global.u32 %0, [%1];" : "=r"(v0) : "l"(f + tid));
            asm volatile("ld.acquire.gpu.global.u32 %0, [%1];" : "=r"(v1) : "l"(f + tid + 32));
            asm volatile("ld.acquire.gpu.global.u32 %0, [%1];" : "=r"(v2) : "l"(f + tid + 64));
            asm volatile("ld.acquire.gpu.global.u32 %0, [%1];" : "=r"(v3) : "l"(f + tid + 96));
            bool ok = (v0 >= target) & (v1 >= target) & (v2 >= target) & (v3 >= target);
            if (__all_sync(0xffffffffu, ok)) break;
        }
    }
    __syncthreads();
}

__global__ void reset_flags_kernel() {
    if (threadIdx.x < NBLK) g_flags[threadIdx.x] = 0u;
}

// ------------------------- embedding gather ----------------------------------
__global__ void gather_kernel(const int* __restrict__ x,
                              const float* __restrict__ emb,
                              float* __restrict__ out) {
    const int total = MM * (HH / 4);
    for (int i = blockIdx.x * blockDim.x + threadIdx.x; i < total;
         i += gridDim.x * blockDim.x) {
        int row = i >> 8;
        int col = i & 255;
        int tok = __ldg(x + row);
        float4 v = __ldg(((const float4*)(emb + (size_t)tok * HH)) + col);
        ((float4*)out)[i] = v;
    }
}

// ------------------------- input GEMM: C = A @ W^T + bias (natural layout) ---
__global__ __launch_bounds__(256) void igemm_kernel(
    const float* __restrict__ A, const float* __restrict__ W,
    const float* __restrict__ bias, float* __restrict__ C) {
    __shared__ float As[16][132];
    __shared__ float Bs[16][132];
    const int tid = threadIdx.x;
    const int bm = blockIdx.y * 128;
    const int bn = blockIdx.x * 128;
    const int tx = tid & 15;
    const int ty = tid >> 4;
    const int r0 = tid >> 2;
    const int kq0 = (tid & 3) << 2;

    ull acc[8][4];
#pragma unroll
    for (int i = 0; i < 8; ++i)
#pragma unroll
        for (int j = 0; j < 4; ++j) acc[i][j] = 0ull;

    for (int k0 = 0; k0 < HH; k0 += 16) {
#pragma unroll
        for (int j = 0; j < 2; ++j) {
            int row = r0 + j * 64;
            float4 va = __ldg((const float4*)(A + (size_t)(bm + row) * HH + k0 + kq0));
            As[kq0 + 0][row] = va.x; As[kq0 + 1][row] = va.y;
            As[kq0 + 2][row] = va.z; As[kq0 + 3][row] = va.w;
            float4 vb = __ldg((const float4*)(W + (size_t)(bn + row) * HH + k0 + kq0));
            Bs[kq0 + 0][row] = vb.x; Bs[kq0 + 1][row] = vb.y;
            Bs[kq0 + 2][row] = vb.z; Bs[kq0 + 3][row] = vb.w;
        }
        __syncthreads();
#pragma unroll
        for (int k = 0; k < 16; ++k) {
            float ra[8];
            *(float4*)(ra)     = *(const float4*)(&As[k][ty * 8]);
            *(float4*)(ra + 4) = *(const float4*)(&As[k][ty * 8 + 4]);
            ulonglong2 rb0 = *(const ulonglong2*)(&Bs[k][tx * 8]);
            ulonglong2 rb1 = *(const ulonglong2*)(&Bs[k][tx * 8 + 4]);
#pragma unroll
            for (int i = 0; i < 8; ++i) {
                ull rad = dup2(ra[i]);
                acc[i][0] = ffma2(rad, rb0.x, acc[i][0]);
                acc[i][1] = ffma2(rad, rb0.y, acc[i][1]);
                acc[i][2] = ffma2(rad, rb1.x, acc[i][2]);
                acc[i][3] = ffma2(rad, rb1.y, acc[i][3]);
            }
        }
        __syncthreads();
    }
#pragma unroll
    for (int i = 0; i < 8; ++i) {
        size_t m = (size_t)(bm + ty * 8 + i);
#pragma unroll
        for (int jp = 0; jp < 4; jp += 2) {
            int n = bn + tx * 8 + jp * 2;
            float4 bv = __ldg((const float4*)(bias + n));
            unsigned l0, h0, l1, h1;
            asm("mov.b64 {%0, %1}, %2;" : "=r"(l0), "=r"(h0) : "l"(acc[i][jp]));
            asm("mov.b64 {%0, %1}, %2;" : "=r"(l1), "=r"(h1) : "l"(acc[i][jp + 1]));
            float4 o;
            o.x = __uint_as_float(l0) + bv.x;
            o.y = __uint_as_float(h0) + bv.y;
            o.z = __uint_as_float(l1) + bv.z;
            o.w = __uint_as_float(h1) + bv.w;
            *(float4*)(C + m * GG + n) = o;
        }
    }
}

// ------------------------- persistent recurrence -----------------------------
// 128 blocks x 512 threads; block owns 8 units = 32 gate rows (row = gate*8+u)
// in padded SMEM (pitch 1028 floats -> conflict-free broadcasts).
// Compute role: thread (pg=tid>>6, ug4=(tid>>3)&7, b4=tid&7) accumulates a
// 4-row x 4-batch f32x2 tile over a 32-K subslice of each 256-K chunk.
// Chunks double-buffered; partials (fp32) alias h-buffer 0 (race-free).
// Final role (tid<256): (fu=tid&7, fb=(tid>>3)&31) -> coalesced G loads,
// 8-partial reduce, cell update, coalesced h store.
__global__ __launch_bounds__(512, 1) void recur_kernel(
    const float* __restrict__ Gin,   // [SQ*BB][GG] natural
    const float* __restrict__ Whh,   // [GG, HH]
    const float* __restrict__ h0,
    const float* __restrict__ c0,
    float* __restrict__ out,         // [SQ,BB,HH]
    float* __restrict__ hT,
    float* __restrict__ cT,
    unsigned flag_base) {
    extern __shared__ __align__(16) char shraw[];
    float*  Wsh = (float*)shraw;                                 // 32 x 1028 = 131584 B
    float4* hb  = (float4*)(shraw + 32 * HPITCH * sizeof(float)); // [2][64][33] f4 = 67584 B
    float*  part = (float*)hb;                                    // alias buffer 0 (33792 B)

    const int tid = threadIdx.x;
    const int u0 = blockIdx.x * 8;
    // compute role
    const int b4  = tid & 7;
    const int ug4 = (tid >> 3) & 7;
    const int pg  = tid >> 6;            // 0..7 K-subslice
    // final role (tid < 256)
    const int fu = tid & 7;
    const int fb = (tid >> 3) & 31;
    // loader role
    const int lb = tid >> 4;             // batch row 0..31
    const int lj = tid & 15;             // float4 col 0..15

    // Load W rows (lr = gate*8 + unit) into padded SMEM
    for (int i = tid; i < 32 * 256; i += 512) {
        int lr = i >> 8;
        int kq = i & 255;
        int gam = lr >> 3, uu = lr & 7;
        float4 v = __ldg((const float4*)(Whh + (size_t)(gam * HH + u0 + uu) * HH) + kq);
        *(float4*)(Wsh + (size_t)lr * HPITCH + kq * 4) = v;
    }
    float c = (c0 != nullptr) ? c0[fb * HH + u0 + fu] : 0.f;
    __syncthreads();

    const float* wbase = Wsh + (size_t)(ug4 * 4) * HPITCH;

    float hlast = 0.f;
    for (int t = 0; t < SQ; ++t) {
        const float* hp = (t == 0) ? h0 : (out + (size_t)(t - 1) * BB * HH);
        // gate preactivations (32B-segment coalesced)
        float a0 = 0.f, a1 = 0.f, a2 = 0.f, a3 = 0.f;
        if (tid < 256) {
            const float* gb = Gin + ((size_t)t * BB + fb) * GG + u0 + fu;
            a0 = __ldcg(gb);
            a1 = __ldcg(gb + HH);
            a2 = __ldcg(gb + 2 * HH);
            a3 = __ldcg(gb + 3 * HH);
        }
        if (hp != nullptr) {
            ull acc[4][4];
#pragma unroll
            for (int rr = 0; rr < 4; ++rr)
#pragma unroll
                for (int ss = 0; ss < 4; ++ss) acc[rr][ss] = 0ull;

            float4 r[4];
#pragma unroll
            for (int m = 0; m < 4; ++m)
                r[m] = __ldcg((const float4*)(hp + (size_t)lb * HH) + lj + 16 * m);
            for (int cI = 0; cI < 4; ++cI) {
                float4* buf = hb + (size_t)(cI & 1) * (64 * 33);
#pragma unroll
                for (int m = 0; m < 4; ++m)
                    buf[(lj + 16 * m) * 33 + lb] = r[m];
                __syncthreads();
                if (cI < 3) {
                    const float* hpc = hp + (cI + 1) * 256;
#pragma unroll
                    for (int m = 0; m < 4; ++m)
                        r[m] = __ldcg((const float4*)(hpc + (size_t)lb * HH) + lj + 16 * m);
                }
                const float* wk = wbase + cI * 256 + pg * 32;
                const float4* hk = buf + (pg * 8) * 33 + b4;
#pragma unroll
                for (int i = 0; i < 8; ++i) {
                    ulonglong2 Wv[4];
#pragma unroll
                    for (int rr = 0; rr < 4; ++rr)
                        Wv[rr] = *(const ulonglong2*)(wk + (size_t)rr * HPITCH + i * 4);
#pragma unroll
                    for (int ss = 0; ss < 4; ++ss) {
                        float4 hv4 = hk[i * 33 + 8 * ss];
                        ulonglong2 Hv = *(ulonglong2*)&hv4;
                        acc[0][ss] = ffma2(Wv[0].x, Hv.x, acc[0][ss]);
                        acc[1][ss] = ffma2(Wv[1].x, Hv.x, acc[1][ss]);
                        acc[2][ss] = ffma2(Wv[2].x, Hv.x, acc[2][ss]);
                        acc[3][ss] = ffma2(Wv[3].x, Hv.x, acc[3][ss]);
                        acc[0][ss] = ffma2(Wv[0].y, Hv.y, acc[0][ss]);
                        acc[1][ss] = ffma2(Wv[1].y, Hv.y, acc[1][ss]);
                        acc[2][ss] = ffma2(Wv[2].y, Hv.y, acc[2][ss]);
                        acc[3][ss] = ffma2(Wv[3].y, Hv.y, acc[3][ss]);
                    }
                }
            }
            // partials into buffer-0 region (free now; see race argument)
#pragma unroll
            for (int rr = 0; rr < 4; ++rr)
#pragma unroll
                for (int ss = 0; ss < 4; ++ss)
                    part[(pg * 32 + ug4 * 4 + rr) * 33 + b4 + 8 * ss] = sum2(acc[rr][ss]);
        }
        __syncthreads();
        if (tid < 256) {
            if (hp != nullptr) {
#pragma unroll
                for (int p = 0; p < 8; ++p) {
                    const float* pp = part + (size_t)p * 32 * 33 + fb;
                    a0 += pp[(0 * 8 + fu) * 33];
                    a1 += pp[(1 * 8 + fu) * 33];
                    a2 += pp[(2 * 8 + fu) * 33];
                    a3 += pp[(3 * 8 + fu) * 33];
                }
            }
            float iv = 1.f / (1.f + expf(-a0));
            float fv = 1.f / (1.f + expf(-a1));
            float gv = tanhf(a2);
            float ov = 1.f / (1.f + expf(-a3));
            c = fv * c + iv * gv;
            float hv = ov * tanhf(c);
            __stcg(out + (size_t)t * BB * HH + (size_t)fb * HH + u0 + fu, hv);
            hlast = hv;
        }
        if (t != SQ - 1) grid_barrier(flag_base + (unsigned)t + 1u);
    }
    if (tid < 256) {
        if (hT != nullptr) hT[fb * HH + u0 + fu] = hlast;
        if (cT != nullptr) cT[fb * HH + u0 + fu] = c;
    }
}

// ------------------------- launch --------------------------------------------
extern "C" void kernel_launch(void* const* d_in, const int* in_sizes, int n_in,
                              void* d_out, int out_size) {
    const int*   x       = (const int*)d_in[0];
    const float* emb_enc = (const float*)d_in[1];
    const float* enc_Wih = (const float*)d_in[2];
    const float* enc_Whh = (const float*)d_in[3];
    const float* enc_b   = (const float*)d_in[4];
    const float* emb_dec = (const float*)d_in[5];
    const float* dec_Wih = (const float*)d_in[6];
    const float* dec_Whh = (const float*)d_in[7];
    const float* dec_b   = (const float*)d_in[8];
    float* out = (float*)d_out;

    float *seqA, *seqB, *seqC, *G, *hT, *cT;
    cudaGetSymbolAddress((void**)&seqA, g_seqA);
    cudaGetSymbolAddress((void**)&seqB, g_seqB);
    cudaGetSymbolAddress((void**)&seqC, g_seqC);
    cudaGetSymbolAddress((void**)&G,    g_G);
    cudaGetSymbolAddress((void**)&hT,   g_hT);
    cudaGetSymbolAddress((void**)&cT,   g_cT);

    const int recur_smem = 32 * HPITCH * (int)sizeof(float)
                         + 2 * 64 * 33 * (int)sizeof(float4);   // 199168 B
    cudaFuncSetAttribute(recur_kernel,
                         cudaFuncAttributeMaxDynamicSharedMemorySize, recur_smem);

    dim3 ig_grid(GG / 128, MM / 128);  // (32, 128)

    gather_kernel<<<2048, 256>>>(x, emb_enc, seqA);
    gather_kernel<<<2048, 256>>>(x, emb_dec, seqC);

    unsigned launch_idx = 0;

    // ---------------- encoder ----------------
    float* cur = seqA;
    float* nxt = seqB;
    for (int l = 0; l < LL; ++l) {
        igemm_kernel<<<ig_grid, 256>>>(cur, enc_Wih + (size_t)l * GG * HH,
                                       enc_b + (size_t)l * GG, G);
        recur_kernel<<<NBLK, 512, recur_smem>>>(
            G, enc_Whh + (size_t)l * GG * HH, nullptr, nullptr,
            nxt, hT + (size_t)l * BB * HH, cT + (size_t)l * BB * HH,
            launch_idx * 1024u);
        ++launch_idx;
        float* tmp = cur; cur = nxt; nxt = tmp;
    }

    // ---------------- decoder ----------------
    cur = seqC; nxt = seqA;
    for (int l = 0; l < LL; ++l) {
        igemm_kernel<<<ig_grid, 256>>>(cur, dec_Wih + (size_t)l * GG * HH,
                                       dec_b + (size_t)l * GG, G);
        float* target = (l == LL - 1) ? out : nxt;
        recur_kernel<<<NBLK, 512, recur_smem>>>(
            G, dec_Whh + (size_t)l * GG * HH,
            hT + (size_t)l * BB * HH, cT + (size_t)l * BB * HH,
            target, nullptr, nullptr,
            launch_idx * 1024u);
        ++launch_idx;
        nxt = cur; cur = target;
    }

    reset_flags_kernel<<<1, 128>>>();
}